// round 16
// baseline (speedup 1.0000x reference)
#include <cuda_runtime.h>
#include <cuda_bf16.h>
#include <stdint.h>
#include <math.h>

// POVMProjector: R=32768, IN=1024, OUT=256
// d_out = [ Re(collapsed) R*1024 | probs R*256 ] (fp32) — confirmed R8.
// R16: mma_gemm restructured to 128 threads / 4 warps, warp tile 64x64
// (better LDSM:HMMA ratio). Rest identical to R15 (gram-trick GEMM2).

#define R_TOT   32768
#define IN_DIM  1024
#define OUT_DIM 256

// ---------------- scratch ----------------
__device__ __nv_bfloat16 g_A1[(size_t)R_TOT * 4096];     // [pr_h|pim_h|pr_l|pim_l]
__device__ __nv_bfloat16 g_B1[(size_t)2 * 256 * 6144];   // z0: re-folded, z1: im-folded
__device__ float         g_I[(size_t)2 * R_TOT * 256];   // inner re, im planes
__device__ __nv_bfloat16 g_A2[(size_t)R_TOT * 512];      // [p_hi|p_lo]
__device__ __nv_bfloat16 g_B2[1280 * 512];               // rows 0-1023: brT [hi|lo]; 1024-1279: G [hi|lo]
__device__ float         g_G[256 * 256];                 // gram bi*bi^T
__device__ float         g_c2[(size_t)R_TOT * 1280];     // [c_re(1024) | q(256)]
__device__ float         g_nsq[(size_t)R_TOT * 16];      // c_re^2 partials

__device__ __forceinline__ uint32_t smem_u32(const void* p) {
    uint32_t a;
    asm("{ .reg .u64 t; cvta.to.shared.u64 t, %1; cvt.u32.u64 %0, t; }" : "=r"(a) : "l"(p));
    return a;
}
#define SWZ(o) ((o) ^ (((o) >> 3) & 0x70))

__device__ __forceinline__ void ldm_x4(uint32_t* r, uint32_t addr) {
    asm volatile("ldmatrix.sync.aligned.m8n8.x4.shared.b16 {%0,%1,%2,%3}, [%4];"
        : "=r"(r[0]), "=r"(r[1]), "=r"(r[2]), "=r"(r[3]) : "r"(addr));
}
__device__ __forceinline__ void mma_bf16(float* d, const uint32_t* a, const uint32_t* b) {
    asm volatile("mma.sync.aligned.m16n8k16.row.col.f32.bf16.bf16.f32 "
        "{%0,%1,%2,%3}, {%4,%5,%6,%7}, {%8,%9}, {%0,%1,%2,%3};"
        : "+f"(d[0]), "+f"(d[1]), "+f"(d[2]), "+f"(d[3])
        : "r"(a[0]), "r"(a[1]), "r"(a[2]), "r"(a[3]), "r"(b[0]), "r"(b[1]));
}
__device__ __forceinline__ void cp16(uint32_t dst, const void* src) {
    asm volatile("cp.async.cg.shared.global [%0], [%1], 16;" :: "r"(dst), "l"(src));
}
#define CP_COMMIT() asm volatile("cp.async.commit_group;" ::: "memory")
#define CP_WAIT(n)  asm volatile("cp.async.wait_group %0;" :: "n"(n) : "memory")

#define STAGE_BYTES 32768
#define NSTAGE      3
#define SM_TOTAL    (STAGE_BYTES * NSTAGE)   // 96 KB

// ---------------------------------------------------------------------------
// Split-bf16 HMMA GEMM. CTA tile 128x128, 128 threads = 4 warps,
// warp tile 64x64 (wm = warp>>1 row half, wn = warp&1 col half).
// Per ks-step: 8 LDSM feed 32 HMMA. 3-stage cp.async ring.
// Plane z: A col offset z*aps, B offset z*bps, C offset z*cps.
// Chunk ch: A col (ch>=awrap? ch-awrap: ch)*64; B col (ch>=bwrap? ch-bwrap: ch)*64.
// ---------------------------------------------------------------------------
__global__ __launch_bounds__(128, 2)
void mma_gemm(const __nv_bfloat16* __restrict__ A, int lda, int aps,
              const __nv_bfloat16* __restrict__ B, int ldb, size_t bps,
              float* __restrict__ C, int ldc, size_t cps,
              int nchunks, int awrap, int bwrap,
              float* __restrict__ nsq, int nsq_ymax)
{
    extern __shared__ __align__(1024) char smem[];

    const int tid  = threadIdx.x;
    const int lane = tid & 31, warp = tid >> 5;
    const int wm   = warp >> 1, wn = warp & 1;      // 2x2 warp grid, 64x64 each
    const int row0 = blockIdx.x * 128;
    const int n0   = blockIdx.y * 128;
    const int z    = blockIdx.z;

    float* Cz = C + (size_t)z * cps;

    float acc[4][8][4];
#pragma unroll
    for (int mt = 0; mt < 4; mt++)
#pragma unroll
        for (int nt = 0; nt < 8; nt++)
#pragma unroll
            for (int j = 0; j < 4; j++) acc[mt][nt][j] = 0.f;

    // loader: thread t owns full row t of A tile and row t of B tile (128B each)
    const __nv_bfloat16* gA = A + (size_t)(row0 + tid) * lda + z * aps;
    const __nv_bfloat16* gB = B + (size_t)z * bps + (size_t)(n0 + tid) * ldb;
    uint32_t stoff[8];
#pragma unroll
    for (int j = 0; j < 8; j++) stoff[j] = SWZ((uint32_t)(tid * 128 + j * 16));

    const uint32_t sm0 = smem_u32(smem);

    // ldmatrix row bases
    uint32_t arow[4], brow[4];
#pragma unroll
    for (int mt = 0; mt < 4; mt++)
        arow[mt] = (uint32_t)((wm * 64 + mt * 16 + (lane & 15)) * 128 + (lane >> 4) * 16);
    {
        const int q = lane >> 3;
#pragma unroll
        for (int p = 0; p < 4; p++)
            brow[p] = (uint32_t)((wn * 64 + p * 16 + ((q & 2) ? 8 : 0) + (lane & 7)) * 128
                                 + (q & 1) * 16);
    }

    auto issue = [&](int ch, int stage) {
        const int ac = (ch >= awrap) ? ch - awrap : ch;
        const int bc = (ch >= bwrap) ? ch - bwrap : ch;
        const char* asrc = (const char*)(gA + ac * 64);
        const char* bsrc = (const char*)(gB + bc * 64);
        const uint32_t ab = sm0 + stage * STAGE_BYTES;
        const uint32_t bb = ab + 16384;
#pragma unroll
        for (int j = 0; j < 8; j++) {
            cp16(ab + stoff[j], asrc + j * 16);
            cp16(bb + stoff[j], bsrc + j * 16);
        }
        CP_COMMIT();
    };

    issue(0, 0);
    if (nchunks > 1) issue(1, 1);

    int stage = 0;
    for (int ch = 0; ch < nchunks; ch++) {
        if (ch + 1 < nchunks) { CP_WAIT(1); } else { CP_WAIT(0); }
        __syncthreads();

        const uint32_t smA_u = sm0 + stage * STAGE_BYTES;
        const uint32_t smB_u = smA_u + 16384;

        if (ch + 2 < nchunks) {
            int ns = stage + 2; if (ns >= NSTAGE) ns -= NSTAGE;
            issue(ch + 2, ns);
        }

#pragma unroll
        for (int ks = 0; ks < 4; ks++) {
            uint32_t afr[4][4];
#pragma unroll
            for (int mt = 0; mt < 4; mt++)
                ldm_x4(afr[mt], smA_u + SWZ(arow[mt] + (uint32_t)ks * 32));
            uint32_t bfr[8][2];
#pragma unroll
            for (int p = 0; p < 4; p++) {
                uint32_t r4[4];
                ldm_x4(r4, smB_u + SWZ(brow[p] + (uint32_t)ks * 32));
                bfr[2*p][0]   = r4[0]; bfr[2*p][1]   = r4[1];
                bfr[2*p+1][0] = r4[2]; bfr[2*p+1][1] = r4[3];
            }
#pragma unroll
            for (int mt = 0; mt < 4; mt++)
#pragma unroll
                for (int nt = 0; nt < 8; nt++)
                    mma_bf16(acc[mt][nt], afr[mt], bfr[nt]);
        }
        stage++; if (stage >= NSTAGE) stage -= NSTAGE;
    }

    const bool do_nsq = (nsq != nullptr) && (blockIdx.y < (unsigned)nsq_ymax);
    const int gid = lane >> 2, tig = lane & 3;
#pragma unroll
    for (int mt = 0; mt < 4; mt++) {
        const int rg = row0 + wm * 64 + mt * 16 + gid;
        float s0 = 0.f, s1 = 0.f;
#pragma unroll
        for (int nt = 0; nt < 8; nt++) {
            const float a0 = acc[mt][nt][0], a1 = acc[mt][nt][1];
            const float a2 = acc[mt][nt][2], a3 = acc[mt][nt][3];
            if (do_nsq) { s0 += a0*a0 + a1*a1; s1 += a2*a2 + a3*a3; }
            const int cg = n0 + wn * 64 + nt * 8 + tig * 2;
            *(float2*)(Cz + (size_t)rg * ldc + cg)       = make_float2(a0, a1);
            *(float2*)(Cz + (size_t)(rg + 8) * ldc + cg) = make_float2(a2, a3);
        }
        if (do_nsq) {
            s0 += __shfl_xor_sync(0xffffffffu, s0, 1);
            s0 += __shfl_xor_sync(0xffffffffu, s0, 2);
            s1 += __shfl_xor_sync(0xffffffffu, s1, 1);
            s1 += __shfl_xor_sync(0xffffffffu, s1, 2);
            if (tig == 0) {
                const int slot = blockIdx.y * 2 + wn;
                g_nsq[(size_t)rg * 16 + slot]       = s0;
                g_nsq[(size_t)(rg + 8) * 16 + slot] = s1;
            }
        }
    }
}

// ---------------- gram: G = bi * bi^T (fp32, 16 CTAs) ----------------
__global__ void gram_fp32(const float* __restrict__ bi)
{
    __shared__ float Sn[64][65];
    __shared__ float Sm[64][65];
    const int tx = threadIdx.x, ty = threadIdx.y;       // 16x16
    const int t  = ty * 16 + tx;
    const int n0 = blockIdx.x * 64, m0 = blockIdx.y * 64;

    float acc[4][4] = {};
    for (int k0 = 0; k0 < 1024; k0 += 64) {
        __syncthreads();
#pragma unroll
        for (int j = 0; j < 16; j++) {
            int idx = t + j * 256;
            int r = idx >> 6, c = idx & 63;
            Sn[r][c] = bi[(size_t)(n0 + r) * 1024 + k0 + c];
            Sm[r][c] = bi[(size_t)(m0 + r) * 1024 + k0 + c];
        }
        __syncthreads();
#pragma unroll 8
        for (int k = 0; k < 64; k++) {
            float a[4], b[4];
#pragma unroll
            for (int i = 0; i < 4; i++) { a[i] = Sn[ty * 4 + i][k]; b[i] = Sm[tx * 4 + i][k]; }
#pragma unroll
            for (int i = 0; i < 4; i++)
#pragma unroll
                for (int j = 0; j < 4; j++) acc[i][j] = fmaf(a[i], b[j], acc[i][j]);
        }
    }
#pragma unroll
    for (int i = 0; i < 4; i++)
#pragma unroll
        for (int j = 0; j < 4; j++)
            g_G[(size_t)(n0 + ty * 4 + i) * 256 + m0 + tx * 4 + j] = acc[i][j];
}

// ---------------- conversions ----------------
__device__ __forceinline__ uint2 pack_hi4(float4 v) {
    __nv_bfloat162 a = __floats2bfloat162_rn(v.x, v.y);
    __nv_bfloat162 b = __floats2bfloat162_rn(v.z, v.w);
    uint2 r; r.x = *(uint32_t*)&a; r.y = *(uint32_t*)&b; return r;
}
__device__ __forceinline__ float4 resid4(float4 v, uint2 h) {
    __nv_bfloat162 a = *(__nv_bfloat162*)&h.x;
    __nv_bfloat162 b = *(__nv_bfloat162*)&h.y;
    return make_float4(v.x - __low2float(a), v.y - __high2float(a),
                       v.z - __low2float(b), v.w - __high2float(b));
}

__global__ void conv_psi(const float* __restrict__ pr, const float* __restrict__ pim)
{
    size_t i4 = (size_t)blockIdx.x * 256 + threadIdx.x;
    float4 a = ((const float4*)pr)[i4];
    float4 b = ((const float4*)pim)[i4];
    size_t row = i4 >> 8;
    int    c   = (int)(i4 & 255) * 4;
    __nv_bfloat16* rp = g_A1 + row * 4096;
    uint2 ah = pack_hi4(a), bh = pack_hi4(b);
    uint2 al = pack_hi4(resid4(a, ah)), bl = pack_hi4(resid4(b, bh));
    *(uint2*)(rp + c)        = ah;
    *(uint2*)(rp + 1024 + c) = bh;
    *(uint2*)(rp + 2048 + c) = al;
    *(uint2*)(rp + 3072 + c) = bl;
}

__global__ void conv_basis1(const float* __restrict__ br, const float* __restrict__ bi)
{
    int idx = blockIdx.x * 256 + threadIdx.x;
    int m = idx >> 10, k = idx & 1023;
    float xr = br[idx], xi = bi[idx];
    __nv_bfloat16 rh = __float2bfloat16(xr);
    __nv_bfloat16 rl = __float2bfloat16(xr - __bfloat162float(rh));
    __nv_bfloat16 ih = __float2bfloat16(xi);
    __nv_bfloat16 il = __float2bfloat16(xi - __bfloat162float(ih));
    __nv_bfloat16 nih = __float2bfloat16(-xi);
    __nv_bfloat16 nil = __float2bfloat16(-xi - __bfloat162float(nih));
    size_t base = (size_t)m * 6144;
    __nv_bfloat16* B0 = g_B1;
    __nv_bfloat16* B1 = g_B1 + (size_t)256 * 6144;
    B0[base + k]        = rh;  B0[base + 1024 + k] = ih;
    B0[base + 2048 + k] = rh;  B0[base + 3072 + k] = ih;
    B0[base + 4096 + k] = rl;  B0[base + 5120 + k] = il;
    B1[base + k]        = nih; B1[base + 1024 + k] = rh;
    B1[base + 2048 + k] = nih; B1[base + 3072 + k] = rh;
    B1[base + 4096 + k] = nil; B1[base + 5120 + k] = rl;
}

__global__ void conv_basis2(const float* __restrict__ br)
{
    int idx = blockIdx.x * 256 + threadIdx.x;
    int n = idx >> 8, m = idx & 255;
    float x = br[(size_t)m * 1024 + n];
    __nv_bfloat16 h = __float2bfloat16(x);
    __nv_bfloat16 l = __float2bfloat16(x - __bfloat162float(h));
    g_B2[(size_t)n * 512 + m]       = h;
    g_B2[(size_t)n * 512 + 256 + m] = l;
}

__global__ void conv_G()
{
    int idx = blockIdx.x * 256 + threadIdx.x;
    int n = idx >> 8, m = idx & 255;
    float x = g_G[idx];
    __nv_bfloat16 h = __float2bfloat16(x);
    __nv_bfloat16 l = __float2bfloat16(x - __bfloat162float(h));
    g_B2[(size_t)(1024 + n) * 512 + m]       = h;
    g_B2[(size_t)(1024 + n) * 512 + 256 + m] = l;
}

__global__ void probs_epi(float* __restrict__ dout)
{
    const int wid = threadIdx.x >> 5, lid = threadIdx.x & 31;
    const size_t row = (size_t)blockIdx.x * 8 + wid;
    const float4* re = (const float4*)(g_I + row * 256);
    const float4* im = (const float4*)(g_I + (size_t)R_TOT * 256 + row * 256);
    float4 r0 = re[lid * 2], r1 = re[lid * 2 + 1];
    float4 i0 = im[lid * 2], i1 = im[lid * 2 + 1];
    float4 p0 = make_float4(r0.x*r0.x + i0.x*i0.x, r0.y*r0.y + i0.y*i0.y,
                            r0.z*r0.z + i0.z*i0.z, r0.w*r0.w + i0.w*i0.w);
    float4 p1 = make_float4(r1.x*r1.x + i1.x*i1.x, r1.y*r1.y + i1.y*i1.y,
                            r1.z*r1.z + i1.z*i1.z, r1.w*r1.w + i1.w*i1.w);
    float s = p0.x + p0.y + p0.z + p0.w + p1.x + p1.y + p1.z + p1.w;
#pragma unroll
    for (int off = 16; off > 0; off >>= 1) s += __shfl_xor_sync(0xffffffffu, s, off);
    const float inv = 1.f / (s + 1e-12f);
    float4 q0 = make_float4(p0.x*inv, p0.y*inv, p0.z*inv, p0.w*inv);
    float4 q1 = make_float4(p1.x*inv, p1.y*inv, p1.z*inv, p1.w*inv);
    float4* pdst = (float4*)(dout + (size_t)R_TOT * 1024 + row * 256);
    pdst[lid * 2]     = q0;
    pdst[lid * 2 + 1] = q1;
    uint2 h0 = pack_hi4(q0), h1 = pack_hi4(q1);
    uint2 l0 = pack_hi4(resid4(q0, h0)), l1 = pack_hi4(resid4(q1, h1));
    *(uint4*)(g_A2 + row * 512 + lid * 8)       = make_uint4(h0.x, h0.y, h1.x, h1.y);
    *(uint4*)(g_A2 + row * 512 + 256 + lid * 8) = make_uint4(l0.x, l0.y, l1.x, l1.y);
}

__global__ void norm_scale(float* __restrict__ dout)
{
    __shared__ float red[8];
    const size_t row = blockIdx.x;
    const int t = threadIdx.x, wid = t >> 5, lid = t & 31;
    const float* probs = dout + (size_t)R_TOT * 1024 + row * 256;
    float v = (t < 16) ? g_nsq[row * 16 + t] : 0.f;
    v += g_c2[row * 1280 + 1024 + t] * probs[t];
#pragma unroll
    for (int off = 16; off > 0; off >>= 1) v += __shfl_xor_sync(0xffffffffu, v, off);
    if (lid == 0) red[wid] = v;
    __syncthreads();
    float tot = red[0] + red[1] + red[2] + red[3] + red[4] + red[5] + red[6] + red[7];
    const float sc = 1.f / (sqrtf(fmaxf(tot, 0.f)) + 1e-12f);
    float4 r = ((const float4*)(g_c2 + row * 1280))[t];
    ((float4*)(dout + row * 1024))[t] =
        make_float4(r.x * sc, r.y * sc, r.z * sc, r.w * sc);
}

// ---------------------------------------------------------------------------
extern "C" void kernel_launch(void* const* d_in, const int* in_sizes, int n_in,
                              void* d_out, int out_size)
{
    const float* pr  = (const float*)d_in[0];
    const float* pim = (const float*)d_in[1];
    const float* br  = (const float*)d_in[2];
    const float* bi  = (const float*)d_in[3];
    float* out = (float*)d_out;

    static int smem_set = 0;
    if (!smem_set) {
        cudaFuncSetAttribute(mma_gemm, cudaFuncAttributeMaxDynamicSharedMemorySize, SM_TOTAL);
        smem_set = 1;
    }

    __nv_bfloat16 *a1, *b1, *a2, *b2;
    float *gI, *c2, *nsq;
    cudaGetSymbolAddress((void**)&a1, g_A1);
    cudaGetSymbolAddress((void**)&b1, g_B1);
    cudaGetSymbolAddress((void**)&a2, g_A2);
    cudaGetSymbolAddress((void**)&b2, g_B2);
    cudaGetSymbolAddress((void**)&gI, g_I);
    cudaGetSymbolAddress((void**)&c2, g_c2);
    cudaGetSymbolAddress((void**)&nsq, g_nsq);

    // conversions + gram
    gram_fp32<<<dim3(4, 4), dim3(16, 16)>>>(bi);
    conv_basis1<<<1024, 256>>>(br, bi);
    conv_basis2<<<1024, 256>>>(br);
    conv_G<<<256, 256>>>();
    conv_psi<<<32768, 256>>>(pr, pim);

    // GEMM1: inner planes = psi x folded-basis^T (96 chunks, awrap=64)
    mma_gemm<<<dim3(R_TOT / 128, 2, 2), 128, SM_TOTAL>>>(
        a1, 4096, 0, b1, 6144, (size_t)256 * 6144,
        gI, 256, (size_t)R_TOT * 256, 96, 64, 96, nullptr, 0);

    // probs + split
    probs_epi<<<R_TOT / 8, 256>>>(out);

    // GEMM2: [c_re | q] = probs x [brT | G]^T  (N=1280, 12 chunks)
    mma_gemm<<<dim3(R_TOT / 128, 10, 1), 128, SM_TOTAL>>>(
        a2, 512, 0, b2, 512, 0,
        c2, 1280, 0, 12, 8, 4, nsq, 8);

    // normalize + emit
    norm_scale<<<R_TOT, 256>>>(out);
}

// round 17
// speedup vs baseline: 1.4719x; 1.4719x over previous
#include <cuda_runtime.h>
#include <cuda_bf16.h>
#include <cuda_fp16.h>
#include <stdint.h>
#include <math.h>

// POVMProjector: R=32768, IN=1024, OUT=256
// d_out = [ Re(collapsed) R*1024 | probs R*256 ] (fp32) — confirmed R8.
// R17: mma_gemm reverted to R15 form (256 thr, frag double-buffer).
// GEMM2 switched to fp16 2-term (p_h*b_h + p_h*b_l): 12 -> 8 chunks.

#define R_TOT   32768
#define IN_DIM  1024
#define OUT_DIM 256

// ---------------- scratch ----------------
__device__ __nv_bfloat16 g_A1[(size_t)R_TOT * 4096];     // [pr_h|pim_h|pr_l|pim_l]
__device__ __nv_bfloat16 g_B1[(size_t)2 * 256 * 6144];   // z0: re-folded, z1: im-folded
__device__ float         g_I[(size_t)2 * R_TOT * 256];   // inner re, im planes
__device__ __half        g_A2[(size_t)R_TOT * 256];      // p (fp16, hi only)
__device__ __half        g_B2[1280 * 512];               // row n: [b_h(256)|b_l(256)]; rows 1024+: G
__device__ float         g_G[256 * 256];                 // gram bi*bi^T
__device__ float         g_c2[(size_t)R_TOT * 1280];     // [c_re(1024) | q(256)]
__device__ float         g_nsq[(size_t)R_TOT * 16];      // c_re^2 partials

__device__ __forceinline__ uint32_t smem_u32(const void* p) {
    uint32_t a;
    asm("{ .reg .u64 t; cvta.to.shared.u64 t, %1; cvt.u32.u64 %0, t; }" : "=r"(a) : "l"(p));
    return a;
}
#define SWZ(o) ((o) ^ (((o) >> 3) & 0x70))

__device__ __forceinline__ void ldm_x4(uint32_t* r, uint32_t addr) {
    asm volatile("ldmatrix.sync.aligned.m8n8.x4.shared.b16 {%0,%1,%2,%3}, [%4];"
        : "=r"(r[0]), "=r"(r[1]), "=r"(r[2]), "=r"(r[3]) : "r"(addr));
}
template<bool HALF>
__device__ __forceinline__ void mma_16816(float* d, const uint32_t* a, const uint32_t* b) {
    if (HALF)
        asm volatile("mma.sync.aligned.m16n8k16.row.col.f32.f16.f16.f32 "
            "{%0,%1,%2,%3}, {%4,%5,%6,%7}, {%8,%9}, {%0,%1,%2,%3};"
            : "+f"(d[0]), "+f"(d[1]), "+f"(d[2]), "+f"(d[3])
            : "r"(a[0]), "r"(a[1]), "r"(a[2]), "r"(a[3]), "r"(b[0]), "r"(b[1]));
    else
        asm volatile("mma.sync.aligned.m16n8k16.row.col.f32.bf16.bf16.f32 "
            "{%0,%1,%2,%3}, {%4,%5,%6,%7}, {%8,%9}, {%0,%1,%2,%3};"
            : "+f"(d[0]), "+f"(d[1]), "+f"(d[2]), "+f"(d[3])
            : "r"(a[0]), "r"(a[1]), "r"(a[2]), "r"(a[3]), "r"(b[0]), "r"(b[1]));
}
__device__ __forceinline__ void cp16(uint32_t dst, const void* src) {
    asm volatile("cp.async.cg.shared.global [%0], [%1], 16;" :: "r"(dst), "l"(src));
}
#define CP_COMMIT() asm volatile("cp.async.commit_group;" ::: "memory")
#define CP_WAIT(n)  asm volatile("cp.async.wait_group %0;" :: "n"(n) : "memory")

#define STAGE_BYTES 32768
#define NSTAGE      3
#define SM_TOTAL    (STAGE_BYTES * NSTAGE)   // 96 KB

// ---------------------------------------------------------------------------
// Split-16bit HMMA GEMM (R15-verified structure; 256 thr, 8 warps = 4Mx2N,
// warp tile 32x64, frag double-buffer, 3-stage cp.async ring).
// Element type is 2 bytes; HALF selects the mma flavor.
// ---------------------------------------------------------------------------
template<bool HALF>
__global__ __launch_bounds__(256)
void mma_gemm(const __nv_bfloat16* __restrict__ A, int lda, int aps,
              const __nv_bfloat16* __restrict__ B, int ldb, size_t bps,
              float* __restrict__ C, int ldc, size_t cps,
              int nchunks, int awrap, int bwrap,
              float* __restrict__ nsq, int nsq_ymax)
{
    extern __shared__ __align__(1024) char smem[];

    const int tid  = threadIdx.x;
    const int lane = tid & 31, warp = tid >> 5;
    const int wm   = warp >> 1, wn = warp & 1;
    const int row0 = blockIdx.x * 128;
    const int n0   = blockIdx.y * 128;
    const int z    = blockIdx.z;

    float* Cz = C + (size_t)z * cps;

    float acc[2][8][4];
#pragma unroll
    for (int mt = 0; mt < 2; mt++)
#pragma unroll
        for (int nt = 0; nt < 8; nt++)
#pragma unroll
            for (int j = 0; j < 4; j++) acc[mt][nt][j] = 0.f;

    const int lr = tid >> 1, lh = tid & 1;
    const __nv_bfloat16* gA = A + (size_t)(row0 + lr) * lda + z * aps + lh * 32;
    const __nv_bfloat16* gB = B + (size_t)z * bps + (size_t)(n0 + lr) * ldb + lh * 32;
    uint32_t stoff[4];
#pragma unroll
    for (int j = 0; j < 4; j++) stoff[j] = SWZ((uint32_t)(lr * 128 + lh * 64 + j * 16));

    const uint32_t sm0 = smem_u32(smem);

    uint32_t arow[2], brow[4];
#pragma unroll
    for (int mt = 0; mt < 2; mt++)
        arow[mt] = (uint32_t)((wm * 32 + mt * 16 + (lane & 15)) * 128 + (lane >> 4) * 16);
    {
        const int q = lane >> 3;
#pragma unroll
        for (int p = 0; p < 4; p++)
            brow[p] = (uint32_t)((wn * 64 + p * 16 + ((q & 2) ? 8 : 0) + (lane & 7)) * 128
                                 + (q & 1) * 16);
    }

    auto issue = [&](int ch, int stage) {
        const int ac = (ch >= awrap) ? ch - awrap : ch;
        const int bc = (ch >= bwrap) ? ch - bwrap : ch;
        const char* asrc = (const char*)(gA + ac * 64);
        const char* bsrc = (const char*)(gB + bc * 64);
        const uint32_t ab = sm0 + stage * STAGE_BYTES;
        const uint32_t bb = ab + 16384;
#pragma unroll
        for (int j = 0; j < 4; j++) {
            cp16(ab + stoff[j], asrc + j * 16);
            cp16(bb + stoff[j], bsrc + j * 16);
        }
        CP_COMMIT();
    };

    uint32_t afr[2][2][4];
    uint32_t bfr[2][8][2];
    auto load_frags = [&](uint32_t smA_u, uint32_t smB_u, int ks, int buf) {
#pragma unroll
        for (int mt = 0; mt < 2; mt++)
            ldm_x4(afr[buf][mt], smA_u + SWZ(arow[mt] + (uint32_t)ks * 32));
#pragma unroll
        for (int p = 0; p < 4; p++) {
            uint32_t r4[4];
            ldm_x4(r4, smB_u + SWZ(brow[p] + (uint32_t)ks * 32));
            bfr[buf][2*p][0]   = r4[0]; bfr[buf][2*p][1]   = r4[1];
            bfr[buf][2*p+1][0] = r4[2]; bfr[buf][2*p+1][1] = r4[3];
        }
    };

    issue(0, 0);
    if (nchunks > 1) issue(1, 1);

    int stage = 0;
    for (int ch = 0; ch < nchunks; ch++) {
        if (ch + 1 < nchunks) { CP_WAIT(1); } else { CP_WAIT(0); }
        __syncthreads();

        const uint32_t smA_u = sm0 + stage * STAGE_BYTES;
        const uint32_t smB_u = smA_u + 16384;

        load_frags(smA_u, smB_u, 0, 0);

        if (ch + 2 < nchunks) {
            int ns = stage + 2; if (ns >= NSTAGE) ns -= NSTAGE;
            issue(ch + 2, ns);
        }

#pragma unroll
        for (int ks = 0; ks < 4; ks++) {
            const int cur = ks & 1;
            if (ks < 3) load_frags(smA_u, smB_u, ks + 1, cur ^ 1);
#pragma unroll
            for (int mt = 0; mt < 2; mt++)
#pragma unroll
                for (int nt = 0; nt < 8; nt++)
                    mma_16816<HALF>(acc[mt][nt], afr[cur][mt], bfr[cur][nt]);
        }
        stage++; if (stage >= NSTAGE) stage -= NSTAGE;
    }

    const bool do_nsq = (nsq != nullptr) && (blockIdx.y < (unsigned)nsq_ymax);
    const int gid = lane >> 2, tig = lane & 3;
#pragma unroll
    for (int mt = 0; mt < 2; mt++) {
        const int rg = row0 + wm * 32 + mt * 16 + gid;
        float s0 = 0.f, s1 = 0.f;
#pragma unroll
        for (int nt = 0; nt < 8; nt++) {
            const float a0 = acc[mt][nt][0], a1 = acc[mt][nt][1];
            const float a2 = acc[mt][nt][2], a3 = acc[mt][nt][3];
            if (do_nsq) { s0 += a0*a0 + a1*a1; s1 += a2*a2 + a3*a3; }
            const int cg = n0 + wn * 64 + nt * 8 + tig * 2;
            *(float2*)(Cz + (size_t)rg * ldc + cg)       = make_float2(a0, a1);
            *(float2*)(Cz + (size_t)(rg + 8) * ldc + cg) = make_float2(a2, a3);
        }
        if (do_nsq) {
            s0 += __shfl_xor_sync(0xffffffffu, s0, 1);
            s0 += __shfl_xor_sync(0xffffffffu, s0, 2);
            s1 += __shfl_xor_sync(0xffffffffu, s1, 1);
            s1 += __shfl_xor_sync(0xffffffffu, s1, 2);
            if (tig == 0) {
                const int slot = blockIdx.y * 2 + wn;
                g_nsq[(size_t)rg * 16 + slot]       = s0;
                g_nsq[(size_t)(rg + 8) * 16 + slot] = s1;
            }
        }
    }
}

// ---------------- gram: G = bi * bi^T (fp32, 16 CTAs) ----------------
__global__ void gram_fp32(const float* __restrict__ bi)
{
    __shared__ float Sn[64][65];
    __shared__ float Sm[64][65];
    const int tx = threadIdx.x, ty = threadIdx.y;       // 16x16
    const int t  = ty * 16 + tx;
    const int n0 = blockIdx.x * 64, m0 = blockIdx.y * 64;

    float acc[4][4] = {};
    for (int k0 = 0; k0 < 1024; k0 += 64) {
        __syncthreads();
#pragma unroll
        for (int j = 0; j < 16; j++) {
            int idx = t + j * 256;
            int r = idx >> 6, c = idx & 63;
            Sn[r][c] = bi[(size_t)(n0 + r) * 1024 + k0 + c];
            Sm[r][c] = bi[(size_t)(m0 + r) * 1024 + k0 + c];
        }
        __syncthreads();
#pragma unroll 8
        for (int k = 0; k < 64; k++) {
            float a[4], b[4];
#pragma unroll
            for (int i = 0; i < 4; i++) { a[i] = Sn[ty * 4 + i][k]; b[i] = Sm[tx * 4 + i][k]; }
#pragma unroll
            for (int i = 0; i < 4; i++)
#pragma unroll
                for (int j = 0; j < 4; j++) acc[i][j] = fmaf(a[i], b[j], acc[i][j]);
        }
    }
#pragma unroll
    for (int i = 0; i < 4; i++)
#pragma unroll
        for (int j = 0; j < 4; j++)
            g_G[(size_t)(n0 + ty * 4 + i) * 256 + m0 + tx * 4 + j] = acc[i][j];
}

// ---------------- conversions ----------------
__device__ __forceinline__ uint2 pack_hi4(float4 v) {
    __nv_bfloat162 a = __floats2bfloat162_rn(v.x, v.y);
    __nv_bfloat162 b = __floats2bfloat162_rn(v.z, v.w);
    uint2 r; r.x = *(uint32_t*)&a; r.y = *(uint32_t*)&b; return r;
}
__device__ __forceinline__ float4 resid4(float4 v, uint2 h) {
    __nv_bfloat162 a = *(__nv_bfloat162*)&h.x;
    __nv_bfloat162 b = *(__nv_bfloat162*)&h.y;
    return make_float4(v.x - __low2float(a), v.y - __high2float(a),
                       v.z - __low2float(b), v.w - __high2float(b));
}
__device__ __forceinline__ uint2 pack_h4(float4 v) {
    __half2 a = __floats2half2_rn(v.x, v.y);
    __half2 b = __floats2half2_rn(v.z, v.w);
    uint2 r; r.x = *(uint32_t*)&a; r.y = *(uint32_t*)&b; return r;
}

__global__ void conv_psi(const float* __restrict__ pr, const float* __restrict__ pim)
{
    size_t i4 = (size_t)blockIdx.x * 256 + threadIdx.x;
    float4 a = ((const float4*)pr)[i4];
    float4 b = ((const float4*)pim)[i4];
    size_t row = i4 >> 8;
    int    c   = (int)(i4 & 255) * 4;
    __nv_bfloat16* rp = g_A1 + row * 4096;
    uint2 ah = pack_hi4(a), bh = pack_hi4(b);
    uint2 al = pack_hi4(resid4(a, ah)), bl = pack_hi4(resid4(b, bh));
    *(uint2*)(rp + c)        = ah;
    *(uint2*)(rp + 1024 + c) = bh;
    *(uint2*)(rp + 2048 + c) = al;
    *(uint2*)(rp + 3072 + c) = bl;
}

__global__ void conv_basis1(const float* __restrict__ br, const float* __restrict__ bi)
{
    int idx = blockIdx.x * 256 + threadIdx.x;
    int m = idx >> 10, k = idx & 1023;
    float xr = br[idx], xi = bi[idx];
    __nv_bfloat16 rh = __float2bfloat16(xr);
    __nv_bfloat16 rl = __float2bfloat16(xr - __bfloat162float(rh));
    __nv_bfloat16 ih = __float2bfloat16(xi);
    __nv_bfloat16 il = __float2bfloat16(xi - __bfloat162float(ih));
    __nv_bfloat16 nih = __float2bfloat16(-xi);
    __nv_bfloat16 nil = __float2bfloat16(-xi - __bfloat162float(nih));
    size_t base = (size_t)m * 6144;
    __nv_bfloat16* B0 = g_B1;
    __nv_bfloat16* B1 = g_B1 + (size_t)256 * 6144;
    B0[base + k]        = rh;  B0[base + 1024 + k] = ih;
    B0[base + 2048 + k] = rh;  B0[base + 3072 + k] = ih;
    B0[base + 4096 + k] = rl;  B0[base + 5120 + k] = il;
    B1[base + k]        = nih; B1[base + 1024 + k] = rh;
    B1[base + 2048 + k] = nih; B1[base + 3072 + k] = rh;
    B1[base + 4096 + k] = nil; B1[base + 5120 + k] = rl;
}

// brT -> g_B2 rows 0-1023 (fp16 [hi|lo])
__global__ void conv_basis2(const float* __restrict__ br)
{
    int idx = blockIdx.x * 256 + threadIdx.x;
    int n = idx >> 8, m = idx & 255;
    float x = br[(size_t)m * 1024 + n];
    __half h = __float2half_rn(x);
    __half l = __float2half_rn(x - __half2float(h));
    g_B2[(size_t)n * 512 + m]       = h;
    g_B2[(size_t)n * 512 + 256 + m] = l;
}

// G -> g_B2 rows 1024-1279 (fp16 [hi|lo])
__global__ void conv_G()
{
    int idx = blockIdx.x * 256 + threadIdx.x;
    int n = idx >> 8, m = idx & 255;
    float x = g_G[idx];
    __half h = __float2half_rn(x);
    __half l = __float2half_rn(x - __half2float(h));
    g_B2[(size_t)(1024 + n) * 512 + m]       = h;
    g_B2[(size_t)(1024 + n) * 512 + 256 + m] = l;
}

// inner planes -> probs (d_out tail) + g_A2 (fp16)
__global__ void probs_epi(float* __restrict__ dout)
{
    const int wid = threadIdx.x >> 5, lid = threadIdx.x & 31;
    const size_t row = (size_t)blockIdx.x * 8 + wid;
    const float4* re = (const float4*)(g_I + row * 256);
    const float4* im = (const float4*)(g_I + (size_t)R_TOT * 256 + row * 256);
    float4 r0 = re[lid * 2], r1 = re[lid * 2 + 1];
    float4 i0 = im[lid * 2], i1 = im[lid * 2 + 1];
    float4 p0 = make_float4(r0.x*r0.x + i0.x*i0.x, r0.y*r0.y + i0.y*i0.y,
                            r0.z*r0.z + i0.z*i0.z, r0.w*r0.w + i0.w*i0.w);
    float4 p1 = make_float4(r1.x*r1.x + i1.x*i1.x, r1.y*r1.y + i1.y*i1.y,
                            r1.z*r1.z + i1.z*i1.z, r1.w*r1.w + i1.w*i1.w);
    float s = p0.x + p0.y + p0.z + p0.w + p1.x + p1.y + p1.z + p1.w;
#pragma unroll
    for (int off = 16; off > 0; off >>= 1) s += __shfl_xor_sync(0xffffffffu, s, off);
    const float inv = 1.f / (s + 1e-12f);
    float4 q0 = make_float4(p0.x*inv, p0.y*inv, p0.z*inv, p0.w*inv);
    float4 q1 = make_float4(p1.x*inv, p1.y*inv, p1.z*inv, p1.w*inv);
    float4* pdst = (float4*)(dout + (size_t)R_TOT * 1024 + row * 256);
    pdst[lid * 2]     = q0;
    pdst[lid * 2 + 1] = q1;
    uint2 h0 = pack_h4(q0), h1 = pack_h4(q1);
    *(uint4*)(g_A2 + row * 256 + lid * 8) = make_uint4(h0.x, h0.y, h1.x, h1.y);
}

__global__ void norm_scale(float* __restrict__ dout)
{
    __shared__ float red[8];
    const size_t row = blockIdx.x;
    const int t = threadIdx.x, wid = t >> 5, lid = t & 31;
    const float* probs = dout + (size_t)R_TOT * 1024 + row * 256;
    float v = (t < 16) ? g_nsq[row * 16 + t] : 0.f;
    v += g_c2[row * 1280 + 1024 + t] * probs[t];
#pragma unroll
    for (int off = 16; off > 0; off >>= 1) v += __shfl_xor_sync(0xffffffffu, v, off);
    if (lid == 0) red[wid] = v;
    __syncthreads();
    float tot = red[0] + red[1] + red[2] + red[3] + red[4] + red[5] + red[6] + red[7];
    const float sc = 1.f / (sqrtf(fmaxf(tot, 0.f)) + 1e-12f);
    float4 r = ((const float4*)(g_c2 + row * 1280))[t];
    ((float4*)(dout + row * 1024))[t] =
        make_float4(r.x * sc, r.y * sc, r.z * sc, r.w * sc);
}

// ---------------------------------------------------------------------------
extern "C" void kernel_launch(void* const* d_in, const int* in_sizes, int n_in,
                              void* d_out, int out_size)
{
    const float* pr  = (const float*)d_in[0];
    const float* pim = (const float*)d_in[1];
    const float* br  = (const float*)d_in[2];
    const float* bi  = (const float*)d_in[3];
    float* out = (float*)d_out;

    static int smem_set = 0;
    if (!smem_set) {
        cudaFuncSetAttribute(mma_gemm<false>, cudaFuncAttributeMaxDynamicSharedMemorySize, SM_TOTAL);
        cudaFuncSetAttribute(mma_gemm<true>,  cudaFuncAttributeMaxDynamicSharedMemorySize, SM_TOTAL);
        smem_set = 1;
    }

    __nv_bfloat16 *a1, *b1;
    __half *a2h; __half *b2h;
    float *gI, *c2, *nsq;
    cudaGetSymbolAddress((void**)&a1, g_A1);
    cudaGetSymbolAddress((void**)&b1, g_B1);
    cudaGetSymbolAddress((void**)&a2h, g_A2);
    cudaGetSymbolAddress((void**)&b2h, g_B2);
    cudaGetSymbolAddress((void**)&gI, g_I);
    cudaGetSymbolAddress((void**)&c2, g_c2);
    cudaGetSymbolAddress((void**)&nsq, g_nsq);

    // conversions + gram
    gram_fp32<<<dim3(4, 4), dim3(16, 16)>>>(bi);
    conv_basis1<<<1024, 256>>>(br, bi);
    conv_basis2<<<1024, 256>>>(br);
    conv_G<<<256, 256>>>();
    conv_psi<<<32768, 256>>>(pr, pim);

    // GEMM1 (bf16 3-term): inner planes = psi x folded-basis^T (96 chunks, awrap=64)
    mma_gemm<false><<<dim3(R_TOT / 128, 2, 2), 256, SM_TOTAL>>>(
        a1, 4096, 0, b1, 6144, (size_t)256 * 6144,
        gI, 256, (size_t)R_TOT * 256, 96, 64, 96, nullptr, 0);

    // probs + fp16 pack
    probs_epi<<<R_TOT / 8, 256>>>(out);

    // GEMM2 (fp16 2-term): [c_re | q] = p_h x [b_h | b_l]  (N=1280, 8 chunks,
    // awrap=4: ch 4-7 reuse A cols 0-255; bwrap=8: B cols 0-511 = [hi|lo])
    mma_gemm<true><<<dim3(R_TOT / 128, 10, 1), 256, SM_TOTAL>>>(
        (const __nv_bfloat16*)a2h, 256, 0, (const __nv_bfloat16*)b2h, 512, 0,
        c2, 1280, 0, 8, 4, 8, nsq, 8);

    // normalize + emit
    norm_scale<<<R_TOT, 256>>>(out);
}